// round 12
// baseline (speedup 1.0000x reference)
#include <cuda_runtime.h>
#include <cuda_bf16.h>
#include <cstdint>

#define BB 8
#define NN 10000
#define EE 160000
#define FF 64
#define BN (BB * NN)          // 80000 nodes
#define BE (BB * EE)          // 1280000 edges
#define SCAN_BLKS ((BN + 1023) / 1024)   // 79

#define FLAG_AGG    (1ULL << 62)
#define FLAG_PREFIX (2ULL << 62)
#define VAL_MASK    ((1ULL << 62) - 1)

typedef unsigned long long u64;
typedef unsigned int u32;

// ---- scratch (device globals; no allocation allowed) ----
__device__ int   g_is64;
__device__ int   g_degi[BN];
__device__ float g_dinv[BN];
__device__ int   g_rowstart[BN];
__device__ u64   g_state[SCAN_BLKS];
__device__ int2  g_rc[BE];             // decoded (row, col)
__device__ int   g_seq[BE];            // within-row sequence number
__device__ int2  g_csr[BE];            // {col, norm-bits} grouped by row
__device__ unsigned short g_tb[BN * FF];  // bf16 post-linear features
__device__ float g_pA[BN * FF];
__device__ float g_pB[BN * FF];

// ---------------------------------------------------------------------------
__device__ __forceinline__ void fma2(u64& acc, u64 a, u64 b) {
    asm("fma.rn.f32x2 %0, %1, %2, %0;" : "+l"(acc) : "l"(a), "l"(b));
}
__device__ __forceinline__ u64 pack2(float lo, float hi) {
    u64 r;
    asm("mov.b64 %0, {%1, %2};" : "=l"(r) : "f"(lo), "f"(hi));
    return r;
}
__device__ __forceinline__ u64 splat(float v) {
    u64 r;
    asm("mov.b64 %0, {%1, %1};" : "=l"(r) : "f"(v));
    return r;
}
__device__ __forceinline__ void unpack2(u64 v, float& lo, float& hi) {
    asm("mov.b64 {%0, %1}, %2;" : "=f"(lo), "=f"(hi) : "l"(v));
}

__device__ __forceinline__ void decode_edge(const void* ei, int e, int is64,
                                            int& r, int& c) {
    if (is64) {
        const long long* p = (const long long*)ei;
        r = (int)p[2 * e];
        c = (int)p[2 * e + 1];
    } else {
        const int* p = (const int*)ei;
        r = p[2 * e];
        c = p[2 * e + 1];
    }
    r = min(max(r, 0), NN - 1);
    c = min(max(c, 0), NN - 1);
    int b = e / EE;
    r += b * NN;
    c += b * NN;
}

// ---------------------------------------------------------------------------
__global__ void setup_k(const void* ei, int* __restrict__ degp) {
    int i = blockIdx.x * blockDim.x + threadIdx.x;
    for (; i < BN; i += gridDim.x * blockDim.x) degp[i] = 0;
    if (blockIdx.x == 0 && threadIdx.x < 32) {
        if (threadIdx.x < SCAN_BLKS) {
            g_state[threadIdx.x] = 0;
            if (threadIdx.x + 32 < SCAN_BLKS) g_state[threadIdx.x + 32] = 0;
            if (threadIdx.x + 64 < SCAN_BLKS) g_state[threadIdx.x + 64] = 0;
        }
        const long long* p = (const long long*)ei;
        long long v0 = p[threadIdx.x];
        long long v1 = p[threadIdx.x + 32];
        bool bad = (v0 < 0) | (v0 >= NN) | (v1 < 0) | (v1 >= NN);
        unsigned m = __ballot_sync(0xffffffffu, bad);
        if (threadIdx.x == 0) g_is64 = (m == 0) ? 1 : 0;
    }
}

// histogram + per-edge sequence number + decoded rc (atomics paid once here)
__global__ void edges_k(const void* __restrict__ ei) {
    int e = blockIdx.x * blockDim.x + threadIdx.x;
    if (e >= BE) return;
    int r, c;
    decode_edge(ei, e, g_is64, r, c);
    int seq = atomicAdd(&g_degi[r], 1);
    g_rc[e]  = make_int2(r, c);
    g_seq[e] = seq;
}

// single-kernel decoupled-lookback scan; fused dinv
__global__ void __launch_bounds__(1024, 1) scan_k() {
    __shared__ int warpsum[32];
    __shared__ int sTot;
    __shared__ u64 sBase;
    int tid = threadIdx.x, lane = tid & 31, wid = tid >> 5;
    int b = blockIdx.x;
    int i = b * 1024 + tid;

    int v = (i < BN) ? g_degi[i] : 0;
    int x = v;
#pragma unroll
    for (int off = 1; off < 32; off <<= 1) {
        int y = __shfl_up_sync(0xffffffffu, x, off);
        if (lane >= off) x += y;
    }
    if (lane == 31) warpsum[wid] = x;
    __syncthreads();

    if (wid == 0) {
        int s = warpsum[lane];
        int xs = s;
#pragma unroll
        for (int off = 1; off < 32; off <<= 1) {
            int y = __shfl_up_sync(0xffffffffu, xs, off);
            if (lane >= off) xs += y;
        }
        warpsum[lane] = xs - s;
        if (lane == 31) sTot = xs;
        __syncwarp();
        int tot = sTot;

        if (b == 0) {
            if (lane == 0) {
                sBase = 0;
                atomicExch(&g_state[0], FLAG_PREFIX | (u64)tot);
            }
        } else {
            if (lane == 0)
                atomicExch(&g_state[b], FLAG_AGG | (u64)tot);
            u64 run = 0;
            int j = b - 1;
            while (true) {
                int idx = j - lane;
                u64 s64;
                if (idx >= 0) {
                    do {
                        s64 = *(volatile u64*)&g_state[idx];
                    } while ((s64 >> 62) == 0);
                } else {
                    s64 = FLAG_PREFIX;
                }
                unsigned f = (unsigned)(s64 >> 62);
                u64 val = s64 & VAL_MASK;
                unsigned pm = __ballot_sync(0xffffffffu, f == 2);
                if (pm) {
                    int lp = __ffs(pm) - 1;
                    u64 c2 = (lane <= lp) ? val : 0;
#pragma unroll
                    for (int o = 16; o; o >>= 1)
                        c2 += __shfl_down_sync(0xffffffffu, c2, o);
                    run += __shfl_sync(0xffffffffu, c2, 0);
                    break;
                } else {
                    u64 c2 = val;
#pragma unroll
                    for (int o = 16; o; o >>= 1)
                        c2 += __shfl_down_sync(0xffffffffu, c2, o);
                    run += __shfl_sync(0xffffffffu, c2, 0);
                    j -= 32;
                }
            }
            if (lane == 0) {
                sBase = run;
                atomicExch(&g_state[b], FLAG_PREFIX | (run + (u64)tot));
            }
        }
    }
    __syncthreads();

    if (i < BN) {
        g_rowstart[i] = (int)sBase + warpsum[wid] + (x - v);
        g_dinv[i] = v > 0 ? rsqrtf((float)v) : 0.f;
    }
}

// atomic-free CSR fill: pos = rowstart[r] + seq[e]
__global__ void fill_k() {
    int e = blockIdx.x * blockDim.x + threadIdx.x;
    if (e >= BE) return;
    int2 rc = g_rc[e];
    int pos = g_rowstart[rc.x] + g_seq[e];
    float nm = g_dinv[rc.x] * g_dinv[rc.y];
    g_csr[pos] = make_int2(rc.y, __float_as_int(nm));
}

// ---------------------------------------------------------------------------
// t = (relu?)(in) @ W^T + b  ->  bf16. Coalesced W staging, row-paired f32x2
// accumulators, LDS.128 x reads. 64 rows/block, 8 rows/thread.
template <bool RELU>
__global__ void __launch_bounds__(256)
linear_k(const float* __restrict__ in, const float* __restrict__ W,
         const float* __restrict__ bias, unsigned short* __restrict__ out) {
    __shared__ float4 sW4[32 * 33];
    __shared__ u64    sxp[32 * 64];
    __shared__ float  sb[64];
    int tid = threadIdx.x;
    int row0 = blockIdx.x * 64;

    {
        const float2* W2 = (const float2*)W;
        for (int idx = tid; idx < 2048; idx += 256) {
            int o  = idx >> 5;
            int kp = idx & 31;
            float2 wv = W2[o * 32 + kp];
            float* base = (float*)&sW4[kp * 33 + (o & 31)];
            if (o < 32) { base[0] = wv.x; base[2] = wv.y; }
            else        { base[1] = wv.x; base[3] = wv.y; }
        }
    }
    if (tid < 64) sb[tid] = bias[tid];
    for (int idx = tid; idx < 2048; idx += 256) {
        int rpg = idx >> 6, k = idx & 63;
        float v0 = in[(size_t)(row0 + 2 * rpg) * 64 + k];
        float v1 = in[(size_t)(row0 + 2 * rpg + 1) * 64 + k];
        if (RELU) { v0 = fmaxf(v0, 0.f); v1 = fmaxf(v1, 0.f); }
        sxp[idx] = pack2(v0, v1);
    }
    __syncthreads();

    int w = tid >> 5, l = tid & 31;
    u64 accL[4], accH[4];
    {
        u64 bL = splat(sb[l]), bH = splat(sb[l + 32]);
#pragma unroll
        for (int rp = 0; rp < 4; rp++) { accL[rp] = bL; accH[rp] = bH; }
    }

    const u64* xbase = sxp + (size_t)(w * 4) * 64;
#pragma unroll
    for (int kq = 0; kq < 16; kq++) {
        float4 wq0 = sW4[(2 * kq) * 33 + l];
        float4 wq1 = sW4[(2 * kq + 1) * 33 + l];
        u64 wl0 = splat(wq0.x), wh0 = splat(wq0.y);
        u64 wl1 = splat(wq0.z), wh1 = splat(wq0.w);
        u64 wl2 = splat(wq1.x), wh2 = splat(wq1.y);
        u64 wl3 = splat(wq1.z), wh3 = splat(wq1.w);
#pragma unroll
        for (int rp = 0; rp < 4; rp++) {
            const ulonglong2* xr = (const ulonglong2*)(xbase + rp * 64 + 4 * kq);
            ulonglong2 p0 = xr[0];
            ulonglong2 p1 = xr[1];
            fma2(accL[rp], p0.x, wl0); fma2(accH[rp], p0.x, wh0);
            fma2(accL[rp], p0.y, wl1); fma2(accH[rp], p0.y, wh1);
            fma2(accL[rp], p1.x, wl2); fma2(accH[rp], p1.x, wh2);
            fma2(accL[rp], p1.y, wl3); fma2(accH[rp], p1.y, wh3);
        }
    }
    int rbase = row0 + w * 8;
#pragma unroll
    for (int rp = 0; rp < 4; rp++) {
        float a, b;
        unpack2(accL[rp], a, b);
        out[(size_t)(rbase + 2 * rp) * 64 + l] =
            __bfloat16_as_ushort(__float2bfloat16(a));
        out[(size_t)(rbase + 2 * rp + 1) * 64 + l] =
            __bfloat16_as_ushort(__float2bfloat16(b));
        unpack2(accH[rp], a, b);
        out[(size_t)(rbase + 2 * rp) * 64 + l + 32] =
            __bfloat16_as_ushort(__float2bfloat16(a));
        out[(size_t)(rbase + 2 * rp + 1) * 64 + l + 32] =
            __bfloat16_as_ushort(__float2bfloat16(b));
    }
}

// ---------------------------------------------------------------------------
// CSR gather SpMM over bf16 t (128B/edge). fp32 accumulate.
__global__ void __launch_bounds__(256)
spmm_k(const unsigned short* __restrict__ tb, float* __restrict__ out) {
    int warp = (blockIdx.x * blockDim.x + threadIdx.x) >> 5;
    if (warp >= BN) return;
    int lane = threadIdx.x & 31;
    int start = g_rowstart[warp];
    int cnt   = g_degi[warp];

    const u32* t32 = (const u32*)tb;
    float acc0 = 0.f, acc1 = 0.f;
    if (cnt > 0) {
        int2 m = __ldg(&g_csr[start]);
#pragma unroll 4
        for (int e = 0; e < cnt; e++) {
            int2 mn = (e + 1 < cnt) ? __ldg(&g_csr[start + e + 1]) : m;
            float nm = __int_as_float(m.y);
            u32 v = __ldg(t32 + (size_t)m.x * 32 + lane);
            acc0 = fmaf(nm, __uint_as_float(v << 16), acc0);
            acc1 = fmaf(nm, __uint_as_float(v & 0xffff0000u), acc1);
            m = mn;
        }
    }
    reinterpret_cast<float2*>(out + (size_t)warp * 64)[lane] =
        make_float2(acc0, acc1);
}

// ---------------------------------------------------------------------------
extern "C" void kernel_launch(void* const* d_in, const int* in_sizes, int n_in,
                              void* d_out, int out_size) {
    const float* x = nullptr;
    const void*  ei = nullptr;
    const float* Ws[3] = {nullptr, nullptr, nullptr};
    const float* bs[3] = {nullptr, nullptr, nullptr};
    int nW = 0, nb = 0;
    for (int i = 0; i < n_in; i++) {
        long long sz = in_sizes[i];
        if (sz == (long long)BN * FF)      x  = (const float*)d_in[i];
        else if (sz == (long long)BE * 2)  ei = d_in[i];
        else if (sz == FF * FF) { if (nW < 3) Ws[nW++] = (const float*)d_in[i]; }
        else if (sz == FF)      { if (nb < 3) bs[nb++] = (const float*)d_in[i]; }
    }
    float* out = (float*)d_out;

    int   *degi;
    unsigned short *tb;
    float *pA, *pB;
    cudaGetSymbolAddress((void**)&degi, g_degi);
    cudaGetSymbolAddress((void**)&tb,   g_tb);
    cudaGetSymbolAddress((void**)&pA,   g_pA);
    cudaGetSymbolAddress((void**)&pB,   g_pB);

    // one-time side-stream + events (handles only; no device allocations)
    static cudaStream_t s1 = nullptr;
    static cudaEvent_t  evFork = nullptr, evJoin = nullptr;
    if (s1 == nullptr) {
        cudaStreamCreateWithFlags(&s1, cudaStreamNonBlocking);
        cudaEventCreateWithFlags(&evFork, cudaEventDisableTiming);
        cudaEventCreateWithFlags(&evJoin, cudaEventDisableTiming);
    }

    const int TPB = 256;
    const int edgeBlocks = (BE + TPB - 1) / TPB;     // 5000
    const int nodeBlocks = (BN + TPB - 1) / TPB;     // 313
    const int spmmBlocks = (BN * 32 + TPB - 1) / TPB;// 10000
    const int linBlocks  = BN / 64;                  // 1250

    // fork: linear1 (only needs x/W1) runs concurrently with CSR build
    cudaEventRecord(evFork, 0);
    cudaStreamWaitEvent(s1, evFork, 0);

    setup_k<<<nodeBlocks, TPB>>>(ei, degi);                     // k0
    edges_k<<<edgeBlocks, TPB>>>(ei);                           // k1
    scan_k <<<SCAN_BLKS, 1024>>>();                             // k2
    fill_k <<<edgeBlocks, TPB>>>();                             // k3 <- ncu

    linear_k<false><<<linBlocks, TPB, 0, s1>>>(x, Ws[0], bs[0], tb); // k4 (s1)
    cudaEventRecord(evJoin, s1);
    cudaStreamWaitEvent(0, evJoin, 0);

    spmm_k<<<spmmBlocks, TPB>>>(tb, pA);                        // k5
    linear_k<true ><<<linBlocks, TPB>>>(pA, Ws[1], bs[1], tb);  // k6
    spmm_k<<<spmmBlocks, TPB>>>(tb, pB);                        // k7
    linear_k<true ><<<linBlocks, TPB>>>(pB, Ws[2], bs[2], tb);  // k8
    spmm_k<<<spmmBlocks, TPB>>>(tb, out);                       // k9
}

// round 13
// speedup vs baseline: 1.3542x; 1.3542x over previous
#include <cuda_runtime.h>
#include <cuda_bf16.h>
#include <cstdint>

#define BB 8
#define NN 10000
#define EE 160000
#define FF 64
#define BN (BB * NN)          // 80000 nodes
#define BE (BB * EE)          // 1280000 edges
#define SCAN_BLKS ((BN + 1023) / 1024)   // 79

#define FLAG_AGG    (1ULL << 62)
#define FLAG_PREFIX (2ULL << 62)
#define VAL_MASK    ((1ULL << 62) - 1)

typedef unsigned long long u64;
typedef unsigned int u32;

// ---- scratch (device globals; no allocation allowed) ----
__device__ int   g_is64;
__device__ int   g_degi[BN];
__device__ float g_dinv[BN];
__device__ int   g_rowstart[BN];
__device__ int   g_cursor[BN];
__device__ u64   g_state[SCAN_BLKS];
__device__ int2  g_csr[BE];            // {col, norm-bits} grouped by row
__device__ unsigned short g_tb[BN * FF];  // bf16 post-linear features
__device__ float g_pA[BN * FF];
__device__ float g_pB[BN * FF];

// ---------------------------------------------------------------------------
__device__ __forceinline__ void fma2(u64& acc, u64 a, u64 b) {
    asm("fma.rn.f32x2 %0, %1, %2, %0;" : "+l"(acc) : "l"(a), "l"(b));
}
__device__ __forceinline__ u64 pack2(float lo, float hi) {
    u64 r;
    asm("mov.b64 %0, {%1, %2};" : "=l"(r) : "f"(lo), "f"(hi));
    return r;
}
__device__ __forceinline__ u64 splat(float v) {
    u64 r;
    asm("mov.b64 %0, {%1, %1};" : "=l"(r) : "f"(v));
    return r;
}
__device__ __forceinline__ void unpack2(u64 v, float& lo, float& hi) {
    asm("mov.b64 {%0, %1}, %2;" : "=f"(lo), "=f"(hi) : "l"(v));
}

__device__ __forceinline__ void decode_edge(const void* ei, int e, int is64,
                                            int& r, int& c) {
    if (is64) {
        const long long* p = (const long long*)ei;
        r = (int)p[2 * e];
        c = (int)p[2 * e + 1];
    } else {
        const int* p = (const int*)ei;
        r = p[2 * e];
        c = p[2 * e + 1];
    }
    r = min(max(r, 0), NN - 1);
    c = min(max(c, 0), NN - 1);
    int b = e / EE;
    r += b * NN;
    c += b * NN;
}

// ---------------------------------------------------------------------------
__global__ void setup_k(const void* ei, int* __restrict__ degp) {
    int i = blockIdx.x * blockDim.x + threadIdx.x;
    for (; i < BN; i += gridDim.x * blockDim.x) degp[i] = 0;
    if (blockIdx.x == 0 && threadIdx.x < 32) {
        if (threadIdx.x < SCAN_BLKS) {
            g_state[threadIdx.x] = 0;
            if (threadIdx.x + 32 < SCAN_BLKS) g_state[threadIdx.x + 32] = 0;
            if (threadIdx.x + 64 < SCAN_BLKS) g_state[threadIdx.x + 64] = 0;
        }
        const long long* p = (const long long*)ei;
        long long v0 = p[threadIdx.x];
        long long v1 = p[threadIdx.x + 32];
        bool bad = (v0 < 0) | (v0 >= NN) | (v1 < 0) | (v1 >= NN);
        unsigned m = __ballot_sync(0xffffffffu, bad);
        if (threadIdx.x == 0) g_is64 = (m == 0) ? 1 : 0;
    }
}

// degree histogram
__global__ void edges_k(const void* __restrict__ ei) {
    int e = blockIdx.x * blockDim.x + threadIdx.x;
    if (e >= BE) return;
    int r, c;
    decode_edge(ei, e, g_is64, r, c);
    atomicAdd(&g_degi[r], 1);
}

// single-kernel decoupled-lookback scan; fused dinv + cursor init
__global__ void __launch_bounds__(1024, 1) scan_k() {
    __shared__ int warpsum[32];
    __shared__ int sTot;
    __shared__ u64 sBase;
    int tid = threadIdx.x, lane = tid & 31, wid = tid >> 5;
    int b = blockIdx.x;
    int i = b * 1024 + tid;

    int v = (i < BN) ? g_degi[i] : 0;
    int x = v;
#pragma unroll
    for (int off = 1; off < 32; off <<= 1) {
        int y = __shfl_up_sync(0xffffffffu, x, off);
        if (lane >= off) x += y;
    }
    if (lane == 31) warpsum[wid] = x;
    __syncthreads();

    if (wid == 0) {
        int s = warpsum[lane];
        int xs = s;
#pragma unroll
        for (int off = 1; off < 32; off <<= 1) {
            int y = __shfl_up_sync(0xffffffffu, xs, off);
            if (lane >= off) xs += y;
        }
        warpsum[lane] = xs - s;
        if (lane == 31) sTot = xs;
        __syncwarp();
        int tot = sTot;

        if (b == 0) {
            if (lane == 0) {
                sBase = 0;
                atomicExch(&g_state[0], FLAG_PREFIX | (u64)tot);
            }
        } else {
            if (lane == 0)
                atomicExch(&g_state[b], FLAG_AGG | (u64)tot);
            u64 run = 0;
            int j = b - 1;
            while (true) {
                int idx = j - lane;
                u64 s64;
                if (idx >= 0) {
                    do {
                        s64 = *(volatile u64*)&g_state[idx];
                    } while ((s64 >> 62) == 0);
                } else {
                    s64 = FLAG_PREFIX;
                }
                unsigned f = (unsigned)(s64 >> 62);
                u64 val = s64 & VAL_MASK;
                unsigned pm = __ballot_sync(0xffffffffu, f == 2);
                if (pm) {
                    int lp = __ffs(pm) - 1;
                    u64 c2 = (lane <= lp) ? val : 0;
#pragma unroll
                    for (int o = 16; o; o >>= 1)
                        c2 += __shfl_down_sync(0xffffffffu, c2, o);
                    run += __shfl_sync(0xffffffffu, c2, 0);
                    break;
                } else {
                    u64 c2 = val;
#pragma unroll
                    for (int o = 16; o; o >>= 1)
                        c2 += __shfl_down_sync(0xffffffffu, c2, o);
                    run += __shfl_sync(0xffffffffu, c2, 0);
                    j -= 32;
                }
            }
            if (lane == 0) {
                sBase = run;
                atomicExch(&g_state[b], FLAG_PREFIX | (run + (u64)tot));
            }
        }
    }
    __syncthreads();

    if (i < BN) {
        int start = (int)sBase + warpsum[wid] + (x - v);
        g_rowstart[i] = start;
        g_cursor[i]   = start;
        g_dinv[i] = v > 0 ? rsqrtf((float)v) : 0.f;
    }
}

// scatter edges into CSR slots (re-decode, atomic cursor)
__global__ void fill_k(const void* __restrict__ ei) {
    int e = blockIdx.x * blockDim.x + threadIdx.x;
    if (e >= BE) return;
    int r, c;
    decode_edge(ei, e, g_is64, r, c);
    int pos = atomicAdd(&g_cursor[r], 1);
    float nm = g_dinv[r] * g_dinv[c];
    g_csr[pos] = make_int2(c, __float_as_int(nm));
}

// ---------------------------------------------------------------------------
// t = (relu?)(in) @ W^T + b -> bf16.  16 rows/thread (8 row-pairs),
// 128 rows/block. Per kq: 8 W-wavefronts amortized over 64 FFMA2
// (0.375 wf/FFMA2 -> FMA-bound).
template <bool RELU>
__global__ void __launch_bounds__(256)
linear_k(const float* __restrict__ in, const float* __restrict__ W,
         const float* __restrict__ bias, unsigned short* __restrict__ out) {
    __shared__ float4 sW4[32 * 33];  // [kp][l] padded
    __shared__ u64    sxp[64 * 64];  // [rpg][k] = (x[2rpg][k], x[2rpg+1][k]) 32KB
    __shared__ float  sb[64];
    int tid = threadIdx.x;
    int row0 = blockIdx.x * 128;

    // W staging: coalesced float2 loads, 4-way-conflict transpose STS
    {
        const float2* W2 = (const float2*)W;
        for (int idx = tid; idx < 2048; idx += 256) {
            int o  = idx >> 5;
            int kp = idx & 31;
            float2 wv = W2[o * 32 + kp];
            float* base = (float*)&sW4[kp * 33 + (o & 31)];
            if (o < 32) { base[0] = wv.x; base[2] = wv.y; }
            else        { base[1] = wv.x; base[3] = wv.y; }
        }
    }
    if (tid < 64) sb[tid] = bias[tid];
    for (int idx = tid; idx < 4096; idx += 256) {
        int rpg = idx >> 6, k = idx & 63;
        float v0 = in[(size_t)(row0 + 2 * rpg) * 64 + k];
        float v1 = in[(size_t)(row0 + 2 * rpg + 1) * 64 + k];
        if (RELU) { v0 = fmaxf(v0, 0.f); v1 = fmaxf(v1, 0.f); }
        sxp[idx] = pack2(v0, v1);
    }
    __syncthreads();

    int w = tid >> 5, l = tid & 31;
    u64 accL[8], accH[8];
    {
        u64 bL = splat(sb[l]), bH = splat(sb[l + 32]);
#pragma unroll
        for (int rp = 0; rp < 8; rp++) { accL[rp] = bL; accH[rp] = bH; }
    }

    const u64* xbase = sxp + (size_t)(w * 8) * 64;
#pragma unroll
    for (int kq = 0; kq < 16; kq++) {
        float4 wq0 = sW4[(2 * kq) * 33 + l];       // k=4kq, 4kq+1
        float4 wq1 = sW4[(2 * kq + 1) * 33 + l];   // k=4kq+2, 4kq+3
        u64 wl0 = splat(wq0.x), wh0 = splat(wq0.y);
        u64 wl1 = splat(wq0.z), wh1 = splat(wq0.w);
        u64 wl2 = splat(wq1.x), wh2 = splat(wq1.y);
        u64 wl3 = splat(wq1.z), wh3 = splat(wq1.w);
#pragma unroll
        for (int rp = 0; rp < 8; rp++) {
            const ulonglong2* xr = (const ulonglong2*)(xbase + rp * 64 + 4 * kq);
            ulonglong2 p0 = xr[0];
            ulonglong2 p1 = xr[1];
            fma2(accL[rp], p0.x, wl0); fma2(accH[rp], p0.x, wh0);
            fma2(accL[rp], p0.y, wl1); fma2(accH[rp], p0.y, wh1);
            fma2(accL[rp], p1.x, wl2); fma2(accH[rp], p1.x, wh2);
            fma2(accL[rp], p1.y, wl3); fma2(accH[rp], p1.y, wh3);
        }
    }
    int rbase = row0 + w * 16;
#pragma unroll
    for (int rp = 0; rp < 8; rp++) {
        float a, b;
        unpack2(accL[rp], a, b);
        out[(size_t)(rbase + 2 * rp) * 64 + l] =
            __bfloat16_as_ushort(__float2bfloat16(a));
        out[(size_t)(rbase + 2 * rp + 1) * 64 + l] =
            __bfloat16_as_ushort(__float2bfloat16(b));
        unpack2(accH[rp], a, b);
        out[(size_t)(rbase + 2 * rp) * 64 + l + 32] =
            __bfloat16_as_ushort(__float2bfloat16(a));
        out[(size_t)(rbase + 2 * rp + 1) * 64 + l + 32] =
            __bfloat16_as_ushort(__float2bfloat16(b));
    }
}

// ---------------------------------------------------------------------------
// CSR gather SpMM over bf16 t (128B/edge). fp32 accumulate.
__global__ void __launch_bounds__(256)
spmm_k(const unsigned short* __restrict__ tb, float* __restrict__ out) {
    int warp = (blockIdx.x * blockDim.x + threadIdx.x) >> 5;
    if (warp >= BN) return;
    int lane = threadIdx.x & 31;
    int start = g_rowstart[warp];
    int cnt   = g_degi[warp];

    const u32* t32 = (const u32*)tb;
    float acc0 = 0.f, acc1 = 0.f;
    if (cnt > 0) {
        int2 m = __ldg(&g_csr[start]);
#pragma unroll 4
        for (int e = 0; e < cnt; e++) {
            int2 mn = (e + 1 < cnt) ? __ldg(&g_csr[start + e + 1]) : m;
            float nm = __int_as_float(m.y);
            u32 v = __ldg(t32 + (size_t)m.x * 32 + lane);
            acc0 = fmaf(nm, __uint_as_float(v << 16), acc0);
            acc1 = fmaf(nm, __uint_as_float(v & 0xffff0000u), acc1);
            m = mn;
        }
    }
    reinterpret_cast<float2*>(out + (size_t)warp * 64)[lane] =
        make_float2(acc0, acc1);
}

// ---------------------------------------------------------------------------
extern "C" void kernel_launch(void* const* d_in, const int* in_sizes, int n_in,
                              void* d_out, int out_size) {
    const float* x = nullptr;
    const void*  ei = nullptr;
    const float* Ws[3] = {nullptr, nullptr, nullptr};
    const float* bs[3] = {nullptr, nullptr, nullptr};
    int nW = 0, nb = 0;
    for (int i = 0; i < n_in; i++) {
        long long sz = in_sizes[i];
        if (sz == (long long)BN * FF)      x  = (const float*)d_in[i];
        else if (sz == (long long)BE * 2)  ei = d_in[i];
        else if (sz == FF * FF) { if (nW < 3) Ws[nW++] = (const float*)d_in[i]; }
        else if (sz == FF)      { if (nb < 3) bs[nb++] = (const float*)d_in[i]; }
    }
    float* out = (float*)d_out;

    int   *degi;
    unsigned short *tb;
    float *pA, *pB;
    cudaGetSymbolAddress((void**)&degi, g_degi);
    cudaGetSymbolAddress((void**)&tb,   g_tb);
    cudaGetSymbolAddress((void**)&pA,   g_pA);
    cudaGetSymbolAddress((void**)&pB,   g_pB);

    const int TPB = 256;
    const int edgeBlocks = (BE + TPB - 1) / TPB;     // 5000
    const int nodeBlocks = (BN + TPB - 1) / TPB;     // 313
    const int spmmBlocks = (BN * 32 + TPB - 1) / TPB;// 10000
    const int linBlocks  = BN / 128;                 // 625

    setup_k<<<nodeBlocks, TPB>>>(ei, degi);                     // 0
    edges_k<<<edgeBlocks, TPB>>>(ei);                           // 1
    scan_k <<<SCAN_BLKS, 1024>>>();                             // 2
    linear_k<false><<<linBlocks, TPB>>>(x, Ws[0], bs[0], tb);   // 3 <- ncu
    fill_k <<<edgeBlocks, TPB>>>(ei);                           // 4
    spmm_k<<<spmmBlocks, TPB>>>(tb, pA);                        // 5
    linear_k<true ><<<linBlocks, TPB>>>(pA, Ws[1], bs[1], tb);  // 6
    spmm_k<<<spmmBlocks, TPB>>>(tb, pB);                        // 7
    linear_k<true ><<<linBlocks, TPB>>>(pB, Ws[2], bs[2], tb);  // 8
    spmm_k<<<spmmBlocks, TPB>>>(tb, out);                       // 9
}

// round 14
// speedup vs baseline: 1.3625x; 1.0061x over previous
#include <cuda_runtime.h>
#include <cuda_bf16.h>
#include <cstdint>

#define BB 8
#define NN 10000
#define EE 160000
#define FF 64
#define BN (BB * NN)          // 80000 nodes
#define BE (BB * EE)          // 1280000 edges
#define SCAN_BLKS ((BN + 1023) / 1024)   // 79

#define FLAG_AGG    (1ULL << 62)
#define FLAG_PREFIX (2ULL << 62)
#define VAL_MASK    ((1ULL << 62) - 1)

typedef unsigned long long u64;
typedef unsigned int u32;

// ---- scratch (device globals; no allocation allowed) ----
__device__ int   g_is64;
__device__ int   g_degi[BN];
__device__ float g_dinv[BN];
__device__ int   g_rowstart[BN];
__device__ int   g_cursor[BN];
__device__ u64   g_state[SCAN_BLKS];
__device__ int2  g_csr[BE];            // {col, norm-bits} grouped by row
__device__ unsigned short g_tb[BN * FF];  // bf16 post-linear features
__device__ float g_pA[BN * FF];
__device__ float g_pB[BN * FF];

// ---------------------------------------------------------------------------
__device__ __forceinline__ void fma2(u64& acc, u64 a, u64 b) {
    asm("fma.rn.f32x2 %0, %1, %2, %0;" : "+l"(acc) : "l"(a), "l"(b));
}
__device__ __forceinline__ u64 pack2(float lo, float hi) {
    u64 r;
    asm("mov.b64 %0, {%1, %2};" : "=l"(r) : "f"(lo), "f"(hi));
    return r;
}
__device__ __forceinline__ u64 splat(float v) {
    u64 r;
    asm("mov.b64 %0, {%1, %1};" : "=l"(r) : "f"(v));
    return r;
}
__device__ __forceinline__ void unpack2(u64 v, float& lo, float& hi) {
    asm("mov.b64 {%0, %1}, %2;" : "=f"(lo), "=f"(hi) : "l"(v));
}

__device__ __forceinline__ void decode_edge(const void* ei, int e, int is64,
                                            int& r, int& c) {
    if (is64) {
        const long long* p = (const long long*)ei;
        r = (int)p[2 * e];
        c = (int)p[2 * e + 1];
    } else {
        const int* p = (const int*)ei;
        r = p[2 * e];
        c = p[2 * e + 1];
    }
    r = min(max(r, 0), NN - 1);
    c = min(max(c, 0), NN - 1);
    int b = e / EE;
    r += b * NN;
    c += b * NN;
}

// ---------------------------------------------------------------------------
__global__ void setup_k(const void* ei, int* __restrict__ degp) {
    int i = blockIdx.x * blockDim.x + threadIdx.x;
    for (; i < BN; i += gridDim.x * blockDim.x) degp[i] = 0;
    if (blockIdx.x == 0 && threadIdx.x < 32) {
        if (threadIdx.x < SCAN_BLKS) {
            g_state[threadIdx.x] = 0;
            if (threadIdx.x + 32 < SCAN_BLKS) g_state[threadIdx.x + 32] = 0;
            if (threadIdx.x + 64 < SCAN_BLKS) g_state[threadIdx.x + 64] = 0;
        }
        const long long* p = (const long long*)ei;
        long long v0 = p[threadIdx.x];
        long long v1 = p[threadIdx.x + 32];
        bool bad = (v0 < 0) | (v0 >= NN) | (v1 < 0) | (v1 >= NN);
        unsigned m = __ballot_sync(0xffffffffu, bad);
        if (threadIdx.x == 0) g_is64 = (m == 0) ? 1 : 0;
    }
}

// degree histogram
__global__ void edges_k(const void* __restrict__ ei) {
    int e = blockIdx.x * blockDim.x + threadIdx.x;
    if (e >= BE) return;
    int r, c;
    decode_edge(ei, e, g_is64, r, c);
    atomicAdd(&g_degi[r], 1);
}

// single-kernel decoupled-lookback scan; fused dinv + cursor init
__global__ void __launch_bounds__(1024, 1) scan_k() {
    __shared__ int warpsum[32];
    __shared__ int sTot;
    __shared__ u64 sBase;
    int tid = threadIdx.x, lane = tid & 31, wid = tid >> 5;
    int b = blockIdx.x;
    int i = b * 1024 + tid;

    int v = (i < BN) ? g_degi[i] : 0;
    int x = v;
#pragma unroll
    for (int off = 1; off < 32; off <<= 1) {
        int y = __shfl_up_sync(0xffffffffu, x, off);
        if (lane >= off) x += y;
    }
    if (lane == 31) warpsum[wid] = x;
    __syncthreads();

    if (wid == 0) {
        int s = warpsum[lane];
        int xs = s;
#pragma unroll
        for (int off = 1; off < 32; off <<= 1) {
            int y = __shfl_up_sync(0xffffffffu, xs, off);
            if (lane >= off) xs += y;
        }
        warpsum[lane] = xs - s;
        if (lane == 31) sTot = xs;
        __syncwarp();
        int tot = sTot;

        if (b == 0) {
            if (lane == 0) {
                sBase = 0;
                atomicExch(&g_state[0], FLAG_PREFIX | (u64)tot);
            }
        } else {
            if (lane == 0)
                atomicExch(&g_state[b], FLAG_AGG | (u64)tot);
            u64 run = 0;
            int j = b - 1;
            while (true) {
                int idx = j - lane;
                u64 s64;
                if (idx >= 0) {
                    do {
                        s64 = *(volatile u64*)&g_state[idx];
                    } while ((s64 >> 62) == 0);
                } else {
                    s64 = FLAG_PREFIX;
                }
                unsigned f = (unsigned)(s64 >> 62);
                u64 val = s64 & VAL_MASK;
                unsigned pm = __ballot_sync(0xffffffffu, f == 2);
                if (pm) {
                    int lp = __ffs(pm) - 1;
                    u64 c2 = (lane <= lp) ? val : 0;
#pragma unroll
                    for (int o = 16; o; o >>= 1)
                        c2 += __shfl_down_sync(0xffffffffu, c2, o);
                    run += __shfl_sync(0xffffffffu, c2, 0);
                    break;
                } else {
                    u64 c2 = val;
#pragma unroll
                    for (int o = 16; o; o >>= 1)
                        c2 += __shfl_down_sync(0xffffffffu, c2, o);
                    run += __shfl_sync(0xffffffffu, c2, 0);
                    j -= 32;
                }
            }
            if (lane == 0) {
                sBase = run;
                atomicExch(&g_state[b], FLAG_PREFIX | (run + (u64)tot));
            }
        }
    }
    __syncthreads();

    if (i < BN) {
        int start = (int)sBase + warpsum[wid] + (x - v);
        g_rowstart[i] = start;
        g_cursor[i]   = start;
        g_dinv[i] = v > 0 ? rsqrtf((float)v) : 0.f;
    }
}

// scatter edges into CSR slots (re-decode, atomic cursor)
__global__ void fill_k(const void* __restrict__ ei) {
    int e = blockIdx.x * blockDim.x + threadIdx.x;
    if (e >= BE) return;
    int r, c;
    decode_edge(ei, e, g_is64, r, c);
    int pos = atomicAdd(&g_cursor[r], 1);
    float nm = g_dinv[r] * g_dinv[c];
    g_csr[pos] = make_int2(c, __float_as_int(nm));
}

// ---------------------------------------------------------------------------
// t = (relu?)(in) @ W^T + b -> bf16.
// R11 inner shape (4 row-pairs / 8 rows per thread, 40 regs) but 512 threads
// per block (16 warps, 128 rows) -> 4 blocks/SM, ~64 warps/SM residency.
template <bool RELU>
__global__ void __launch_bounds__(512)
linear_k(const float* __restrict__ in, const float* __restrict__ W,
         const float* __restrict__ bias, unsigned short* __restrict__ out) {
    __shared__ float4 sW4[32 * 33];  // [kp][l] padded
    __shared__ u64    sxp[64 * 64];  // [rpg][k] = (x[2rpg][k], x[2rpg+1][k]) 32KB
    __shared__ float  sb[64];
    int tid = threadIdx.x;
    int row0 = blockIdx.x * 128;

    // W staging: coalesced float2 loads, 4-way-conflict transpose STS
    {
        const float2* W2 = (const float2*)W;
        for (int idx = tid; idx < 2048; idx += 512) {
            int o  = idx >> 5;
            int kp = idx & 31;
            float2 wv = W2[o * 32 + kp];
            float* base = (float*)&sW4[kp * 33 + (o & 31)];
            if (o < 32) { base[0] = wv.x; base[2] = wv.y; }
            else        { base[1] = wv.x; base[3] = wv.y; }
        }
    }
    if (tid < 64) sb[tid] = bias[tid];
    for (int idx = tid; idx < 4096; idx += 512) {
        int rpg = idx >> 6, k = idx & 63;
        float v0 = in[(size_t)(row0 + 2 * rpg) * 64 + k];
        float v1 = in[(size_t)(row0 + 2 * rpg + 1) * 64 + k];
        if (RELU) { v0 = fmaxf(v0, 0.f); v1 = fmaxf(v1, 0.f); }
        sxp[idx] = pack2(v0, v1);
    }
    __syncthreads();

    int w = tid >> 5, l = tid & 31;   // w in 0..15
    u64 accL[4], accH[4];
    {
        u64 bL = splat(sb[l]), bH = splat(sb[l + 32]);
#pragma unroll
        for (int rp = 0; rp < 4; rp++) { accL[rp] = bL; accH[rp] = bH; }
    }

    const u64* xbase = sxp + (size_t)(w * 4) * 64;
#pragma unroll
    for (int kq = 0; kq < 16; kq++) {
        float4 wq0 = sW4[(2 * kq) * 33 + l];       // k=4kq, 4kq+1
        float4 wq1 = sW4[(2 * kq + 1) * 33 + l];   // k=4kq+2, 4kq+3
        u64 wl0 = splat(wq0.x), wh0 = splat(wq0.y);
        u64 wl1 = splat(wq0.z), wh1 = splat(wq0.w);
        u64 wl2 = splat(wq1.x), wh2 = splat(wq1.y);
        u64 wl3 = splat(wq1.z), wh3 = splat(wq1.w);
#pragma unroll
        for (int rp = 0; rp < 4; rp++) {
            const ulonglong2* xr = (const ulonglong2*)(xbase + rp * 64 + 4 * kq);
            ulonglong2 p0 = xr[0];
            ulonglong2 p1 = xr[1];
            fma2(accL[rp], p0.x, wl0); fma2(accH[rp], p0.x, wh0);
            fma2(accL[rp], p0.y, wl1); fma2(accH[rp], p0.y, wh1);
            fma2(accL[rp], p1.x, wl2); fma2(accH[rp], p1.x, wh2);
            fma2(accL[rp], p1.y, wl3); fma2(accH[rp], p1.y, wh3);
        }
    }
    int rbase = row0 + w * 8;
#pragma unroll
    for (int rp = 0; rp < 4; rp++) {
        float a, b;
        unpack2(accL[rp], a, b);
        out[(size_t)(rbase + 2 * rp) * 64 + l] =
            __bfloat16_as_ushort(__float2bfloat16(a));
        out[(size_t)(rbase + 2 * rp + 1) * 64 + l] =
            __bfloat16_as_ushort(__float2bfloat16(b));
        unpack2(accH[rp], a, b);
        out[(size_t)(rbase + 2 * rp) * 64 + l + 32] =
            __bfloat16_as_ushort(__float2bfloat16(a));
        out[(size_t)(rbase + 2 * rp + 1) * 64 + l + 32] =
            __bfloat16_as_ushort(__float2bfloat16(b));
    }
}

// ---------------------------------------------------------------------------
// CSR gather SpMM over bf16 t (128B/edge). fp32 accumulate.
__global__ void __launch_bounds__(256)
spmm_k(const unsigned short* __restrict__ tb, float* __restrict__ out) {
    int warp = (blockIdx.x * blockDim.x + threadIdx.x) >> 5;
    if (warp >= BN) return;
    int lane = threadIdx.x & 31;
    int start = g_rowstart[warp];
    int cnt   = g_degi[warp];

    const u32* t32 = (const u32*)tb;
    float acc0 = 0.f, acc1 = 0.f;
    if (cnt > 0) {
        int2 m = __ldg(&g_csr[start]);
#pragma unroll 4
        for (int e = 0; e < cnt; e++) {
            int2 mn = (e + 1 < cnt) ? __ldg(&g_csr[start + e + 1]) : m;
            float nm = __int_as_float(m.y);
            u32 v = __ldg(t32 + (size_t)m.x * 32 + lane);
            acc0 = fmaf(nm, __uint_as_float(v << 16), acc0);
            acc1 = fmaf(nm, __uint_as_float(v & 0xffff0000u), acc1);
            m = mn;
        }
    }
    reinterpret_cast<float2*>(out + (size_t)warp * 64)[lane] =
        make_float2(acc0, acc1);
}

// ---------------------------------------------------------------------------
extern "C" void kernel_launch(void* const* d_in, const int* in_sizes, int n_in,
                              void* d_out, int out_size) {
    const float* x = nullptr;
    const void*  ei = nullptr;
    const float* Ws[3] = {nullptr, nullptr, nullptr};
    const float* bs[3] = {nullptr, nullptr, nullptr};
    int nW = 0, nb = 0;
    for (int i = 0; i < n_in; i++) {
        long long sz = in_sizes[i];
        if (sz == (long long)BN * FF)      x  = (const float*)d_in[i];
        else if (sz == (long long)BE * 2)  ei = d_in[i];
        else if (sz == FF * FF) { if (nW < 3) Ws[nW++] = (const float*)d_in[i]; }
        else if (sz == FF)      { if (nb < 3) bs[nb++] = (const float*)d_in[i]; }
    }
    float* out = (float*)d_out;

    int   *degi;
    unsigned short *tb;
    float *pA, *pB;
    cudaGetSymbolAddress((void**)&degi, g_degi);
    cudaGetSymbolAddress((void**)&tb,   g_tb);
    cudaGetSymbolAddress((void**)&pA,   g_pA);
    cudaGetSymbolAddress((void**)&pB,   g_pB);

    const int TPB = 256;
    const int edgeBlocks = (BE + TPB - 1) / TPB;     // 5000
    const int nodeBlocks = (BN + TPB - 1) / TPB;     // 313
    const int spmmBlocks = (BN * 32 + TPB - 1) / TPB;// 10000
    const int linBlocks  = BN / 128;                 // 625

    setup_k<<<nodeBlocks, TPB>>>(ei, degi);                     // 0
    edges_k<<<edgeBlocks, TPB>>>(ei);                           // 1
    scan_k <<<SCAN_BLKS, 1024>>>();                             // 2
    linear_k<false><<<linBlocks, 512>>>(x, Ws[0], bs[0], tb);   // 3 <- ncu
    fill_k <<<edgeBlocks, TPB>>>(ei);                           // 4
    spmm_k<<<spmmBlocks, TPB>>>(tb, pA);                        // 5
    linear_k<true ><<<linBlocks, 512>>>(pA, Ws[1], bs[1], tb);  // 6
    spmm_k<<<spmmBlocks, TPB>>>(tb, pB);                        // 7
    linear_k<true ><<<linBlocks, 512>>>(pB, Ws[2], bs[2], tb);  // 8
    spmm_k<<<spmmBlocks, TPB>>>(tb, out);                       // 9
}